// round 12
// baseline (speedup 1.0000x reference)
#include <cuda_runtime.h>
#include <cstdint>

// Problem constants (fixed by setup_inputs)
#define BATCH 4
#define NPTS  16384
#define NTOT  (BATCH * NPTS)   // 65536
#define NJ    1024
#define CCOND 69
#define HID   256
#define TOPK  5

// Scratch (device global; no dynamic allocation allowed)
__device__ float gT[BATCH * NJ * 12];     // top 3x4 rows of final transforms

// ---------------------------------------------------------------------------
// Rodrigues exactly as reference.
// ---------------------------------------------------------------------------
__device__ __forceinline__ void rodrigues_mat(float a0, float a1, float a2, float* R) {
    float e0 = a0 + 1e-8f, e1 = a1 + 1e-8f, e2 = a2 + 1e-8f;
    float angle = sqrtf(e0 * e0 + e1 * e1 + e2 * e2);
    float half = 0.5f * angle;
    float s = sinf(half), c = cosf(half);
    float inv = 1.0f / angle;
    float qw = c, qx = s * a0 * inv, qy = s * a1 * inv, qz = s * a2 * inv;
    float qn = rsqrtf(qw * qw + qx * qx + qy * qy + qz * qz);
    qw *= qn; qx *= qn; qy *= qn; qz *= qn;
    float w2 = qw * qw, x2 = qx * qx, y2 = qy * qy, z2 = qz * qz;
    float wx = qw * qx, wy = qw * qy, wz = qw * qz;
    float xy = qx * qy, xz = qx * qz, yz = qy * qz;
    R[0] = w2 + x2 - y2 - z2; R[1] = 2.f * xy - 2.f * wz; R[2] = 2.f * wy + 2.f * xz;
    R[3] = 2.f * wz + 2.f * xy; R[4] = w2 - x2 + y2 - z2; R[5] = 2.f * yz - 2.f * wx;
    R[6] = 2.f * xz - 2.f * wy; R[7] = 2.f * wx + 2.f * yz; R[8] = w2 - x2 - y2 + z2;
}

// ---------------------------------------------------------------------------
// Fused kernel AB (unchanged): one block = (b, 8 j's), 256 threads.
// ---------------------------------------------------------------------------
__global__ __launch_bounds__(256) void tmat_fused_kernel(
        const float* __restrict__ cond,
        const float* __restrict__ W1,
        const float* __restrict__ b1,
        const float* __restrict__ W2,
        const float* __restrict__ nodes,
        const float* __restrict__ root,
        const float* __restrict__ trans,
        const float* __restrict__ scale,
        const float* __restrict__ b2) {
    __shared__ float4 sP[HID];
    __shared__ float  sW2[HID * 8];
    __shared__ float  sRr[9];
    __shared__ float  sAux[4];

    int b = blockIdx.x >> 7;
    int jbase = (blockIdx.x & 127) << 3;
    int t = threadIdx.x;
    const float* cb = cond + b * CCOND;

    float s0 = 0.f, s1 = 0.f, s2 = 0.f, s3 = 0.f;
    #pragma unroll
    for (int c = 0; c < 68; c += 4) {
        s0 = fmaf(cb[c + 0], W1[(3 + c) * HID + t], s0);
        s1 = fmaf(cb[c + 1], W1[(4 + c) * HID + t], s1);
        s2 = fmaf(cb[c + 2], W1[(5 + c) * HID + t], s2);
        s3 = fmaf(cb[c + 3], W1[(6 + c) * HID + t], s3);
    }
    s0 = fmaf(cb[68], W1[71 * HID + t], s0);
    float base = b1[t] + ((s0 + s1) + (s2 + s3));
    sP[t] = make_float4(W1[t], W1[HID + t], W1[2 * HID + t], base);

    #pragma unroll
    for (int o = 0; o < 6; o++) sW2[t * 8 + o] = W2[t * 6 + o];
    sW2[t * 8 + 6] = 0.f;
    sW2[t * 8 + 7] = 0.f;

    if (t == 0) {
        float R[9];
        rodrigues_mat(root[b * 3], root[b * 3 + 1], root[b * 3 + 2], R);
        #pragma unroll
        for (int i = 0; i < 9; i++) sRr[i] = R[i];
        sAux[0] = scale[b];
        sAux[1] = trans[b * 3 + 0];
        sAux[2] = trans[b * 3 + 1];
        sAux[3] = trans[b * 3 + 2];
    }
    __syncthreads();

    int w = t >> 5;
    int lane = t & 31;
    int j = jbase + w;

    float n0 = nodes[j * 3], n1 = nodes[j * 3 + 1], n2 = nodes[j * 3 + 2];
    float a0 = 0.f, a1 = 0.f, a2 = 0.f, a3 = 0.f, a4 = 0.f, a5 = 0.f;

    #pragma unroll
    for (int i = 0; i < 8; i++) {
        int tt = lane + (i << 5);
        float4 p = sP[tt];
        float h = fmaf(n0, p.x, fmaf(n1, p.y, fmaf(n2, p.z, p.w)));
        h = fmaxf(h, 0.f);
        const float4* w2v = (const float4*)(sW2 + tt * 8);
        float4 lo = w2v[0];
        float4 hi = w2v[1];
        a0 = fmaf(h, lo.x, a0); a1 = fmaf(h, lo.y, a1); a2 = fmaf(h, lo.z, a2);
        a3 = fmaf(h, lo.w, a3); a4 = fmaf(h, hi.x, a4); a5 = fmaf(h, hi.y, a5);
    }
    #pragma unroll
    for (int off = 16; off; off >>= 1) {
        a0 += __shfl_xor_sync(0xffffffffu, a0, off);
        a1 += __shfl_xor_sync(0xffffffffu, a1, off);
        a2 += __shfl_xor_sync(0xffffffffu, a2, off);
        a3 += __shfl_xor_sync(0xffffffffu, a3, off);
        a4 += __shfl_xor_sync(0xffffffffu, a4, off);
        a5 += __shfl_xor_sync(0xffffffffu, a5, off);
    }
    if (lane == 0) {
        float r0 = a0 + b2[0], r1 = a1 + b2[1], r2 = a2 + b2[2];
        float u0 = a3 + b2[3], u1 = a4 + b2[4], u2 = a5 + b2[5];
        float R[9];
        rodrigues_mat(r0, r1, r2, R);
        float s = sAux[0];
        float M[12];
        #pragma unroll
        for (int r = 0; r < 3; r++) {
            float c0 = sRr[r * 3], c1 = sRr[r * 3 + 1], c2 = sRr[r * 3 + 2];
            M[r * 4 + 0] = s * (c0 * R[0] + c1 * R[3] + c2 * R[6]);
            M[r * 4 + 1] = s * (c0 * R[1] + c1 * R[4] + c2 * R[7]);
            M[r * 4 + 2] = s * (c0 * R[2] + c1 * R[5] + c2 * R[8]);
            M[r * 4 + 3] = s * (c0 * u0 + c1 * u1 + c2 * u2) + sAux[1 + r] * s;
        }
        float4* dst = (float4*)(gT + ((size_t)((b << 10) + j)) * 12);
        dst[0] = make_float4(M[0], M[1], M[2], M[3]);
        dst[1] = make_float4(M[4], M[5], M[6], M[7]);
        dst[2] = make_float4(M[8], M[9], M[10], M[11]);
    }
}

// Narrowing merge of a sorted-5 list (b0<=..<=b4) into sorted top-5 p0..p4.
__device__ __forceinline__ void merge5(float& p0, float& p1, float& p2,
                                       float& p3, float& p4,
                                       float b0, float b1, float b2,
                                       float b3, float b4) {
    float n0 = fminf(p0, b0);
    float n1 = fmaxf(p0, fminf(p1, b0));
    float n2 = fmaxf(p1, fminf(p2, b0));
    float n3 = fmaxf(p2, fminf(p3, b0));
    float n4 = fmaxf(p3, fminf(p4, b0));
    float m1 = fminf(n1, b1);
    float m2 = fmaxf(n1, fminf(n2, b1));
    float m3 = fmaxf(n2, fminf(n3, b1));
    float m4 = fmaxf(n3, fminf(n4, b1));
    float k2 = fminf(m2, b2);
    float k3 = fmaxf(m2, fminf(m3, b2));
    float k4 = fmaxf(m3, fminf(m4, b2));
    float l3 = fminf(k3, b3);
    float l4 = fmaxf(k3, fminf(k4, b3));
    p0 = n0; p1 = m1; p2 = k2; p3 = l3;
    p4 = fmaxf(l3, fminf(l4, b4));
}

// sorted-6 insert of packed chunk-min
#define INS6(c0, c1, c2, c3, c4, c5, f) {            \
    float _n0 = fminf(c0, f);                        \
    float _n1 = fmaxf(c0, fminf(c1, f));             \
    float _n2 = fmaxf(c1, fminf(c2, f));             \
    float _n3 = fmaxf(c2, fminf(c3, f));             \
    float _n4 = fmaxf(c3, fminf(c4, f));             \
    float _n5 = fmaxf(c4, fminf(c5, f));             \
    c0 = _n0; c1 = _n1; c2 = _n2; c3 = _n3; c4 = _n4; c5 = _n5; }

// ---------------------------------------------------------------------------
// Kernel C: 256 threads = 128 points x 4 candidate-segments, TWO points per
// thread (pA = lpt, pB = lpt+64) so each LDS.128 of sn[] feeds both points
// (R9 post-mortem: LDS-throughput-bound at L1=76%).
// Two-level exact selection per point per segment:
//  Pass 1: chunk-of-4 min, 6-bit chunk id packed in low mantissa, sorted
//          top-6 chunk list (lemma: true top-5 lies in top-5-by-min chunks;
//          6th chunk = quantization margin).
//  Pass 2: exact rescan of 6 surviving chunks with 10-bit-packed metrics.
// Segment lists merged via smem; winners' exact distances recomputed.
// Grid: 512 blocks x 256 threads.
// ---------------------------------------------------------------------------
__global__ __launch_bounds__(256, 4) void knn_kernel(
        const float* __restrict__ x,
        const float* __restrict__ nodes,
        float* __restrict__ out) {
    __shared__ float4 sn[NJ];
    __shared__ float  mbuf[128][17];   // 3 foreign segs * 5 per point
    int tid = threadIdx.x;
    for (int e = tid; e < NJ; e += 256) {
        float v0 = nodes[e * 3], v1 = nodes[e * 3 + 1], v2 = nodes[e * 3 + 2];
        sn[e] = make_float4(-2.f * v0, -2.f * v1, -2.f * v2,
                            v0 * v0 + v1 * v1 + v2 * v2);
    }
    __syncthreads();

    int lpt = tid & 63;
    int seg = tid >> 6;                  // 0..3
    int pA = blockIdx.x * 128 + lpt;     // first point
    int pB = pA + 64;                    // second point
    float ax = x[pA * 3], ay = x[pA * 3 + 1], az = x[pA * 3 + 2];
    float bx = x[pB * 3], by = x[pB * 3 + 1], bz = x[pB * 3 + 2];
    int jbase = seg << 8;                // 256 candidates per segment

    // ---- Pass 1: top-6 chunks by chunk-min, both points ----
    float A0 = 1e30f, A1 = 1e30f, A2 = 1e30f, A3 = 1e30f, A4 = 1e30f, A5 = 1e30f;
    float B0 = 1e30f, B1 = 1e30f, B2 = 1e30f, B3 = 1e30f, B4 = 1e30f, B5 = 1e30f;

    #pragma unroll 2
    for (int c = 0; c < 64; c++) {
        int j = jbase + (c << 2);
        float4 q0 = sn[j], q1 = sn[j + 1], q2 = sn[j + 2], q3 = sn[j + 3];

        float tA0 = fmaf(ax, q0.x, fmaf(ay, q0.y, fmaf(az, q0.z, q0.w)));
        float tA1 = fmaf(ax, q1.x, fmaf(ay, q1.y, fmaf(az, q1.z, q1.w)));
        float tA2 = fmaf(ax, q2.x, fmaf(ay, q2.y, fmaf(az, q2.z, q2.w)));
        float tA3 = fmaf(ax, q3.x, fmaf(ay, q3.y, fmaf(az, q3.z, q3.w)));
        float mA = fminf(fminf(tA0, tA1), fminf(tA2, tA3));
        float fA = __uint_as_float((__float_as_uint(mA) & 0xFFFFFFC0u) | (unsigned)c);
        INS6(A0, A1, A2, A3, A4, A5, fA);

        float tB0 = fmaf(bx, q0.x, fmaf(by, q0.y, fmaf(bz, q0.z, q0.w)));
        float tB1 = fmaf(bx, q1.x, fmaf(by, q1.y, fmaf(bz, q1.z, q1.w)));
        float tB2 = fmaf(bx, q2.x, fmaf(by, q2.y, fmaf(bz, q2.z, q2.w)));
        float tB3 = fmaf(bx, q3.x, fmaf(by, q3.y, fmaf(bz, q3.z, q3.w)));
        float mB = fminf(fminf(tB0, tB1), fminf(tB2, tB3));
        float fB = __uint_as_float((__float_as_uint(mB) & 0xFFFFFFC0u) | (unsigned)c);
        INS6(B0, B1, B2, B3, B4, B5, fB);
    }

    // ---- Pass 2: exact rescan of surviving chunks, both points ----
    float pa0 = 1e30f, pa1 = 1e30f, pa2 = 1e30f, pa3 = 1e30f, pa4 = 1e30f;
    float pb0 = 1e30f, pb1 = 1e30f, pb2 = 1e30f, pb3 = 1e30f, pb4 = 1e30f;
    {
        float cl[6] = {A0, A1, A2, A3, A4, A5};
        #pragma unroll
        for (int s = 0; s < 6; s++) {
            int j = jbase + (((int)(__float_as_uint(cl[s]) & 63u)) << 2);
            #pragma unroll
            for (int u = 0; u < 4; u++) {
                float4 q = sn[j + u];
                float t = fmaf(ax, q.x, fmaf(ay, q.y, fmaf(az, q.z, q.w)));
                float f = __uint_as_float((__float_as_uint(t) & 0xFFFFFC00u) |
                                          (unsigned)(j + u));
                float n0 = fminf(pa0, f);
                float n1 = fmaxf(pa0, fminf(pa1, f));
                float n2 = fmaxf(pa1, fminf(pa2, f));
                float n3 = fmaxf(pa2, fminf(pa3, f));
                float n4 = fmaxf(pa3, fminf(pa4, f));
                pa0 = n0; pa1 = n1; pa2 = n2; pa3 = n3; pa4 = n4;
            }
        }
    }
    {
        float cl[6] = {B0, B1, B2, B3, B4, B5};
        #pragma unroll
        for (int s = 0; s < 6; s++) {
            int j = jbase + (((int)(__float_as_uint(cl[s]) & 63u)) << 2);
            #pragma unroll
            for (int u = 0; u < 4; u++) {
                float4 q = sn[j + u];
                float t = fmaf(bx, q.x, fmaf(by, q.y, fmaf(bz, q.z, q.w)));
                float f = __uint_as_float((__float_as_uint(t) & 0xFFFFFC00u) |
                                          (unsigned)(j + u));
                float n0 = fminf(pb0, f);
                float n1 = fmaxf(pb0, fminf(pb1, f));
                float n2 = fmaxf(pb1, fminf(pb2, f));
                float n3 = fmaxf(pb2, fminf(pb3, f));
                float n4 = fmaxf(pb3, fminf(pb4, f));
                pb0 = n0; pb1 = n1; pb2 = n2; pb3 = n3; pb4 = n4;
            }
        }
    }

    if (seg != 0) {
        int o = (seg - 1) * 5;
        mbuf[lpt][o + 0] = pa0; mbuf[lpt][o + 1] = pa1; mbuf[lpt][o + 2] = pa2;
        mbuf[lpt][o + 3] = pa3; mbuf[lpt][o + 4] = pa4;
        mbuf[lpt + 64][o + 0] = pb0; mbuf[lpt + 64][o + 1] = pb1;
        mbuf[lpt + 64][o + 2] = pb2; mbuf[lpt + 64][o + 3] = pb3;
        mbuf[lpt + 64][o + 4] = pb4;
    }
    __syncthreads();

    if (seg == 0) {
        #pragma unroll
        for (int s = 0; s < 3; s++) {
            int o = s * 5;
            merge5(pa0, pa1, pa2, pa3, pa4,
                   mbuf[lpt][o + 0], mbuf[lpt][o + 1], mbuf[lpt][o + 2],
                   mbuf[lpt][o + 3], mbuf[lpt][o + 4]);
            merge5(pb0, pb1, pb2, pb3, pb4,
                   mbuf[lpt + 64][o + 0], mbuf[lpt + 64][o + 1],
                   mbuf[lpt + 64][o + 2], mbuf[lpt + 64][o + 3],
                   mbuf[lpt + 64][o + 4]);
        }

        #pragma unroll
        for (int pt = 0; pt < 2; pt++) {
            int p = pt ? pB : pA;
            float x0 = pt ? bx : ax, x1 = pt ? by : ay, x2 = pt ? bz : az;
            float pk[TOPK];
            if (pt) { pk[0] = pb0; pk[1] = pb1; pk[2] = pb2; pk[3] = pb3; pk[4] = pb4; }
            else    { pk[0] = pa0; pk[1] = pa1; pk[2] = pa2; pk[3] = pa3; pk[4] = pa4; }

            int b = p >> 14;
            float xx = x0 * x0 + x1 * x1 + x2 * x2;
            float wsum = 0.f, o0 = 0.f, o1 = 0.f, o2 = 0.f;
            #pragma unroll
            for (int k = 0; k < TOPK; k++) {
                int jk = (int)(__float_as_uint(pk[k]) & 1023u);
                float4 q = sn[jk];
                float t = fmaf(x0, q.x, fmaf(x1, q.y, fmaf(x2, q.z, q.w)));
                float dd = fmaxf(t + xx, 0.f);
                float dist = sqrtf(dd);
                float wk = -logf(fminf(dist, 1.f) - 1e-6f);
                wsum += wk;
                const float4* Tp = (const float4*)(gT + ((size_t)((b << 10) + jk)) * 12);
                float4 r0 = Tp[0], r1 = Tp[1], r2 = Tp[2];
                o0 = fmaf(wk, fmaf(r0.x, x0, fmaf(r0.y, x1, fmaf(r0.z, x2, r0.w))), o0);
                o1 = fmaf(wk, fmaf(r1.x, x0, fmaf(r1.y, x1, fmaf(r1.z, x2, r1.w))), o1);
                o2 = fmaf(wk, fmaf(r2.x, x0, fmaf(r2.y, x1, fmaf(r2.z, x2, r2.w))), o2);
            }
            float inv = 1.f / wsum;
            out[p * 3 + 0] = o0 * inv;
            out[p * 3 + 1] = o1 * inv;
            out[p * 3 + 2] = o2 * inv;
        }
    }
}

// ---------------------------------------------------------------------------
// Inputs (metadata order): x, cond_smpl, nodes, smpl_root_orient, smpl_trans,
// scale, W1, b1, W2, b2.  Output: float32 (B, N, 3).
// ---------------------------------------------------------------------------
extern "C" void kernel_launch(void* const* d_in, const int* in_sizes, int n_in,
                              void* d_out, int out_size) {
    const float* x     = (const float*)d_in[0];
    const float* cond  = (const float*)d_in[1];
    const float* nodes = (const float*)d_in[2];
    const float* root  = (const float*)d_in[3];
    const float* trans = (const float*)d_in[4];
    const float* scale = (const float*)d_in[5];
    const float* W1    = (const float*)d_in[6];
    const float* b1    = (const float*)d_in[7];
    const float* W2    = (const float*)d_in[8];
    const float* b2    = (const float*)d_in[9];
    float* out = (float*)d_out;

    tmat_fused_kernel<<<BATCH * 128, 256>>>(cond, W1, b1, W2, nodes,
                                            root, trans, scale, b2);
    knn_kernel<<<NTOT / 128, 256>>>(x, nodes, out);
}

// round 13
// speedup vs baseline: 1.1477x; 1.1477x over previous
#include <cuda_runtime.h>
#include <cstdint>

// Problem constants (fixed by setup_inputs)
#define BATCH 4
#define NPTS  16384
#define NTOT  (BATCH * NPTS)   // 65536
#define NJ    1024
#define CCOND 69
#define HID   256
#define TOPK  5

// Scratch (device global; no dynamic allocation allowed)
__device__ float gT[BATCH * NJ * 12];     // top 3x4 rows of final transforms

// ---------------------------------------------------------------------------
// Rodrigues exactly as reference.
// ---------------------------------------------------------------------------
__device__ __forceinline__ void rodrigues_mat(float a0, float a1, float a2, float* R) {
    float e0 = a0 + 1e-8f, e1 = a1 + 1e-8f, e2 = a2 + 1e-8f;
    float angle = sqrtf(e0 * e0 + e1 * e1 + e2 * e2);
    float half = 0.5f * angle;
    float s = sinf(half), c = cosf(half);
    float inv = 1.0f / angle;
    float qw = c, qx = s * a0 * inv, qy = s * a1 * inv, qz = s * a2 * inv;
    float qn = rsqrtf(qw * qw + qx * qx + qy * qy + qz * qz);
    qw *= qn; qx *= qn; qy *= qn; qz *= qn;
    float w2 = qw * qw, x2 = qx * qx, y2 = qy * qy, z2 = qz * qz;
    float wx = qw * qx, wy = qw * qy, wz = qw * qz;
    float xy = qx * qy, xz = qx * qz, yz = qy * qz;
    R[0] = w2 + x2 - y2 - z2; R[1] = 2.f * xy - 2.f * wz; R[2] = 2.f * wy + 2.f * xz;
    R[3] = 2.f * wz + 2.f * xy; R[4] = w2 - x2 + y2 - z2; R[5] = 2.f * yz - 2.f * wx;
    R[6] = 2.f * xz - 2.f * wy; R[7] = 2.f * wx + 2.f * yz; R[8] = w2 - x2 - y2 + z2;
}

// ---------------------------------------------------------------------------
// Fused kernel AB (unchanged): one block = (b, 8 j's), 256 threads.
// ---------------------------------------------------------------------------
__global__ __launch_bounds__(256) void tmat_fused_kernel(
        const float* __restrict__ cond,
        const float* __restrict__ W1,
        const float* __restrict__ b1,
        const float* __restrict__ W2,
        const float* __restrict__ nodes,
        const float* __restrict__ root,
        const float* __restrict__ trans,
        const float* __restrict__ scale,
        const float* __restrict__ b2) {
    __shared__ float4 sP[HID];
    __shared__ float  sW2[HID * 8];
    __shared__ float  sRr[9];
    __shared__ float  sAux[4];

    int b = blockIdx.x >> 7;
    int jbase = (blockIdx.x & 127) << 3;
    int t = threadIdx.x;
    const float* cb = cond + b * CCOND;

    float s0 = 0.f, s1 = 0.f, s2 = 0.f, s3 = 0.f;
    #pragma unroll
    for (int c = 0; c < 68; c += 4) {
        s0 = fmaf(cb[c + 0], W1[(3 + c) * HID + t], s0);
        s1 = fmaf(cb[c + 1], W1[(4 + c) * HID + t], s1);
        s2 = fmaf(cb[c + 2], W1[(5 + c) * HID + t], s2);
        s3 = fmaf(cb[c + 3], W1[(6 + c) * HID + t], s3);
    }
    s0 = fmaf(cb[68], W1[71 * HID + t], s0);
    float base = b1[t] + ((s0 + s1) + (s2 + s3));
    sP[t] = make_float4(W1[t], W1[HID + t], W1[2 * HID + t], base);

    #pragma unroll
    for (int o = 0; o < 6; o++) sW2[t * 8 + o] = W2[t * 6 + o];
    sW2[t * 8 + 6] = 0.f;
    sW2[t * 8 + 7] = 0.f;

    if (t == 0) {
        float R[9];
        rodrigues_mat(root[b * 3], root[b * 3 + 1], root[b * 3 + 2], R);
        #pragma unroll
        for (int i = 0; i < 9; i++) sRr[i] = R[i];
        sAux[0] = scale[b];
        sAux[1] = trans[b * 3 + 0];
        sAux[2] = trans[b * 3 + 1];
        sAux[3] = trans[b * 3 + 2];
    }
    __syncthreads();

    int w = t >> 5;
    int lane = t & 31;
    int j = jbase + w;

    float n0 = nodes[j * 3], n1 = nodes[j * 3 + 1], n2 = nodes[j * 3 + 2];
    float a0 = 0.f, a1 = 0.f, a2 = 0.f, a3 = 0.f, a4 = 0.f, a5 = 0.f;

    #pragma unroll
    for (int i = 0; i < 8; i++) {
        int tt = lane + (i << 5);
        float4 p = sP[tt];
        float h = fmaf(n0, p.x, fmaf(n1, p.y, fmaf(n2, p.z, p.w)));
        h = fmaxf(h, 0.f);
        const float4* w2v = (const float4*)(sW2 + tt * 8);
        float4 lo = w2v[0];
        float4 hi = w2v[1];
        a0 = fmaf(h, lo.x, a0); a1 = fmaf(h, lo.y, a1); a2 = fmaf(h, lo.z, a2);
        a3 = fmaf(h, lo.w, a3); a4 = fmaf(h, hi.x, a4); a5 = fmaf(h, hi.y, a5);
    }
    #pragma unroll
    for (int off = 16; off; off >>= 1) {
        a0 += __shfl_xor_sync(0xffffffffu, a0, off);
        a1 += __shfl_xor_sync(0xffffffffu, a1, off);
        a2 += __shfl_xor_sync(0xffffffffu, a2, off);
        a3 += __shfl_xor_sync(0xffffffffu, a3, off);
        a4 += __shfl_xor_sync(0xffffffffu, a4, off);
        a5 += __shfl_xor_sync(0xffffffffu, a5, off);
    }
    if (lane == 0) {
        float r0 = a0 + b2[0], r1 = a1 + b2[1], r2 = a2 + b2[2];
        float u0 = a3 + b2[3], u1 = a4 + b2[4], u2 = a5 + b2[5];
        float R[9];
        rodrigues_mat(r0, r1, r2, R);
        float s = sAux[0];
        float M[12];
        #pragma unroll
        for (int r = 0; r < 3; r++) {
            float c0 = sRr[r * 3], c1 = sRr[r * 3 + 1], c2 = sRr[r * 3 + 2];
            M[r * 4 + 0] = s * (c0 * R[0] + c1 * R[3] + c2 * R[6]);
            M[r * 4 + 1] = s * (c0 * R[1] + c1 * R[4] + c2 * R[7]);
            M[r * 4 + 2] = s * (c0 * R[2] + c1 * R[5] + c2 * R[8]);
            M[r * 4 + 3] = s * (c0 * u0 + c1 * u1 + c2 * u2) + sAux[1 + r] * s;
        }
        float4* dst = (float4*)(gT + ((size_t)((b << 10) + j)) * 12);
        dst[0] = make_float4(M[0], M[1], M[2], M[3]);
        dst[1] = make_float4(M[4], M[5], M[6], M[7]);
        dst[2] = make_float4(M[8], M[9], M[10], M[11]);
    }
}

// Narrowing merge of a sorted-5 list (b0<=..<=b4) into sorted top-5 p0..p4.
__device__ __forceinline__ void merge5(float& p0, float& p1, float& p2,
                                       float& p3, float& p4,
                                       float b0, float b1, float b2,
                                       float b3, float b4) {
    float n0 = fminf(p0, b0);
    float n1 = fmaxf(p0, fminf(p1, b0));
    float n2 = fmaxf(p1, fminf(p2, b0));
    float n3 = fmaxf(p2, fminf(p3, b0));
    float n4 = fmaxf(p3, fminf(p4, b0));
    float m1 = fminf(n1, b1);
    float m2 = fmaxf(n1, fminf(n2, b1));
    float m3 = fmaxf(n2, fminf(n3, b1));
    float m4 = fmaxf(n3, fminf(n4, b1));
    float k2 = fminf(m2, b2);
    float k3 = fmaxf(m2, fminf(m3, b2));
    float k4 = fmaxf(m3, fminf(m4, b2));
    float l3 = fminf(k3, b3);
    float l4 = fmaxf(k3, fminf(k4, b3));
    p0 = n0; p1 = m1; p2 = k2; p3 = l3;
    p4 = fmaxf(l3, fminf(l4, b4));
}

// sorted-6 insert of packed chunk-min
#define INS6(c0, c1, c2, c3, c4, c5, f) {            \
    float _n0 = fminf(c0, f);                        \
    float _n1 = fmaxf(c0, fminf(c1, f));             \
    float _n2 = fmaxf(c1, fminf(c2, f));             \
    float _n3 = fmaxf(c2, fminf(c3, f));             \
    float _n4 = fmaxf(c3, fminf(c4, f));             \
    float _n5 = fmaxf(c4, fminf(c5, f));             \
    c0 = _n0; c1 = _n1; c2 = _n2; c3 = _n3; c4 = _n4; c5 = _n5; }

// ---------------------------------------------------------------------------
// Kernel C: 128 threads = 32 point-pairs x 4 candidate-segments; TWO points
// per thread (pA = lpt, pB = pA+32) so each LDS.128 feeds both points.
// R12 post-mortem: 256-thread blocks at 61 regs left grid at 3.5 blocks/SM
// (occ 30%); 128-thread blocks + grid 1024 restore ~48% occ at identical
// per-candidate cost.
// Two-level exact selection per point per segment:
//  Pass 1: chunk-of-4 min, 6-bit chunk id packed in low mantissa, sorted
//          top-6 chunk list. Pass 2: exact rescan of 6 surviving chunks with
//          10-bit-packed metrics. Segments merged via smem; winners' exact
//          distances recomputed.
// Grid: 1024 blocks x 128 threads.
// ---------------------------------------------------------------------------
__global__ __launch_bounds__(128, 8) void knn_kernel(
        const float* __restrict__ x,
        const float* __restrict__ nodes,
        float* __restrict__ out) {
    __shared__ float4 sn[NJ];
    __shared__ float  mbuf[64][17];   // 3 foreign segs * 5 per point
    int tid = threadIdx.x;
    for (int e = tid; e < NJ; e += 128) {
        float v0 = nodes[e * 3], v1 = nodes[e * 3 + 1], v2 = nodes[e * 3 + 2];
        sn[e] = make_float4(-2.f * v0, -2.f * v1, -2.f * v2,
                            v0 * v0 + v1 * v1 + v2 * v2);
    }
    __syncthreads();

    int lpt = tid & 31;
    int seg = tid >> 5;                  // 0..3
    int pA = blockIdx.x * 64 + lpt;      // first point
    int pB = pA + 32;                    // second point
    float ax = x[pA * 3], ay = x[pA * 3 + 1], az = x[pA * 3 + 2];
    float bx = x[pB * 3], by = x[pB * 3 + 1], bz = x[pB * 3 + 2];
    int jbase = seg << 8;                // 256 candidates per segment

    // ---- Pass 1: top-6 chunks by chunk-min, both points ----
    float A0 = 1e30f, A1 = 1e30f, A2 = 1e30f, A3 = 1e30f, A4 = 1e30f, A5 = 1e30f;
    float B0 = 1e30f, B1 = 1e30f, B2 = 1e30f, B3 = 1e30f, B4 = 1e30f, B5 = 1e30f;

    #pragma unroll 4
    for (int c = 0; c < 64; c++) {
        int j = jbase + (c << 2);
        float4 q0 = sn[j], q1 = sn[j + 1], q2 = sn[j + 2], q3 = sn[j + 3];

        float tA0 = fmaf(ax, q0.x, fmaf(ay, q0.y, fmaf(az, q0.z, q0.w)));
        float tA1 = fmaf(ax, q1.x, fmaf(ay, q1.y, fmaf(az, q1.z, q1.w)));
        float tA2 = fmaf(ax, q2.x, fmaf(ay, q2.y, fmaf(az, q2.z, q2.w)));
        float tA3 = fmaf(ax, q3.x, fmaf(ay, q3.y, fmaf(az, q3.z, q3.w)));
        float tB0 = fmaf(bx, q0.x, fmaf(by, q0.y, fmaf(bz, q0.z, q0.w)));
        float tB1 = fmaf(bx, q1.x, fmaf(by, q1.y, fmaf(bz, q1.z, q1.w)));
        float tB2 = fmaf(bx, q2.x, fmaf(by, q2.y, fmaf(bz, q2.z, q2.w)));
        float tB3 = fmaf(bx, q3.x, fmaf(by, q3.y, fmaf(bz, q3.z, q3.w)));

        float mA = fminf(fminf(tA0, tA1), fminf(tA2, tA3));
        float mB = fminf(fminf(tB0, tB1), fminf(tB2, tB3));
        float fA = __uint_as_float((__float_as_uint(mA) & 0xFFFFFFC0u) | (unsigned)c);
        float fB = __uint_as_float((__float_as_uint(mB) & 0xFFFFFFC0u) | (unsigned)c);
        INS6(A0, A1, A2, A3, A4, A5, fA);
        INS6(B0, B1, B2, B3, B4, B5, fB);
    }

    // ---- Pass 2: exact rescan of surviving chunks, both points ----
    float pa0 = 1e30f, pa1 = 1e30f, pa2 = 1e30f, pa3 = 1e30f, pa4 = 1e30f;
    float pb0 = 1e30f, pb1 = 1e30f, pb2 = 1e30f, pb3 = 1e30f, pb4 = 1e30f;
    {
        float cl[6] = {A0, A1, A2, A3, A4, A5};
        #pragma unroll
        for (int s = 0; s < 6; s++) {
            int j = jbase + (((int)(__float_as_uint(cl[s]) & 63u)) << 2);
            #pragma unroll
            for (int u = 0; u < 4; u++) {
                float4 q = sn[j + u];
                float t = fmaf(ax, q.x, fmaf(ay, q.y, fmaf(az, q.z, q.w)));
                float f = __uint_as_float((__float_as_uint(t) & 0xFFFFFC00u) |
                                          (unsigned)(j + u));
                float n0 = fminf(pa0, f);
                float n1 = fmaxf(pa0, fminf(pa1, f));
                float n2 = fmaxf(pa1, fminf(pa2, f));
                float n3 = fmaxf(pa2, fminf(pa3, f));
                float n4 = fmaxf(pa3, fminf(pa4, f));
                pa0 = n0; pa1 = n1; pa2 = n2; pa3 = n3; pa4 = n4;
            }
        }
    }
    {
        float cl[6] = {B0, B1, B2, B3, B4, B5};
        #pragma unroll
        for (int s = 0; s < 6; s++) {
            int j = jbase + (((int)(__float_as_uint(cl[s]) & 63u)) << 2);
            #pragma unroll
            for (int u = 0; u < 4; u++) {
                float4 q = sn[j + u];
                float t = fmaf(bx, q.x, fmaf(by, q.y, fmaf(bz, q.z, q.w)));
                float f = __uint_as_float((__float_as_uint(t) & 0xFFFFFC00u) |
                                          (unsigned)(j + u));
                float n0 = fminf(pb0, f);
                float n1 = fmaxf(pb0, fminf(pb1, f));
                float n2 = fmaxf(pb1, fminf(pb2, f));
                float n3 = fmaxf(pb2, fminf(pb3, f));
                float n4 = fmaxf(pb3, fminf(pb4, f));
                pb0 = n0; pb1 = n1; pb2 = n2; pb3 = n3; pb4 = n4;
            }
        }
    }

    if (seg != 0) {
        int o = (seg - 1) * 5;
        mbuf[lpt][o + 0] = pa0; mbuf[lpt][o + 1] = pa1; mbuf[lpt][o + 2] = pa2;
        mbuf[lpt][o + 3] = pa3; mbuf[lpt][o + 4] = pa4;
        mbuf[lpt + 32][o + 0] = pb0; mbuf[lpt + 32][o + 1] = pb1;
        mbuf[lpt + 32][o + 2] = pb2; mbuf[lpt + 32][o + 3] = pb3;
        mbuf[lpt + 32][o + 4] = pb4;
    }
    __syncthreads();

    if (seg == 0) {
        #pragma unroll
        for (int s = 0; s < 3; s++) {
            int o = s * 5;
            merge5(pa0, pa1, pa2, pa3, pa4,
                   mbuf[lpt][o + 0], mbuf[lpt][o + 1], mbuf[lpt][o + 2],
                   mbuf[lpt][o + 3], mbuf[lpt][o + 4]);
            merge5(pb0, pb1, pb2, pb3, pb4,
                   mbuf[lpt + 32][o + 0], mbuf[lpt + 32][o + 1],
                   mbuf[lpt + 32][o + 2], mbuf[lpt + 32][o + 3],
                   mbuf[lpt + 32][o + 4]);
        }

        #pragma unroll
        for (int pt = 0; pt < 2; pt++) {
            int p = pt ? pB : pA;
            float x0 = pt ? bx : ax, x1 = pt ? by : ay, x2 = pt ? bz : az;
            float pk[TOPK];
            if (pt) { pk[0] = pb0; pk[1] = pb1; pk[2] = pb2; pk[3] = pb3; pk[4] = pb4; }
            else    { pk[0] = pa0; pk[1] = pa1; pk[2] = pa2; pk[3] = pa3; pk[4] = pa4; }

            int b = p >> 14;
            float xx = x0 * x0 + x1 * x1 + x2 * x2;
            float wsum = 0.f, o0 = 0.f, o1 = 0.f, o2 = 0.f;
            #pragma unroll
            for (int k = 0; k < TOPK; k++) {
                int jk = (int)(__float_as_uint(pk[k]) & 1023u);
                float4 q = sn[jk];
                float t = fmaf(x0, q.x, fmaf(x1, q.y, fmaf(x2, q.z, q.w)));
                float dd = fmaxf(t + xx, 0.f);
                float dist = sqrtf(dd);
                float wk = -logf(fminf(dist, 1.f) - 1e-6f);
                wsum += wk;
                const float4* Tp = (const float4*)(gT + ((size_t)((b << 10) + jk)) * 12);
                float4 r0 = Tp[0], r1 = Tp[1], r2 = Tp[2];
                o0 = fmaf(wk, fmaf(r0.x, x0, fmaf(r0.y, x1, fmaf(r0.z, x2, r0.w))), o0);
                o1 = fmaf(wk, fmaf(r1.x, x0, fmaf(r1.y, x1, fmaf(r1.z, x2, r1.w))), o1);
                o2 = fmaf(wk, fmaf(r2.x, x0, fmaf(r2.y, x1, fmaf(r2.z, x2, r2.w))), o2);
            }
            float inv = 1.f / wsum;
            out[p * 3 + 0] = o0 * inv;
            out[p * 3 + 1] = o1 * inv;
            out[p * 3 + 2] = o2 * inv;
        }
    }
}

// ---------------------------------------------------------------------------
// Inputs (metadata order): x, cond_smpl, nodes, smpl_root_orient, smpl_trans,
// scale, W1, b1, W2, b2.  Output: float32 (B, N, 3).
// ---------------------------------------------------------------------------
extern "C" void kernel_launch(void* const* d_in, const int* in_sizes, int n_in,
                              void* d_out, int out_size) {
    const float* x     = (const float*)d_in[0];
    const float* cond  = (const float*)d_in[1];
    const float* nodes = (const float*)d_in[2];
    const float* root  = (const float*)d_in[3];
    const float* trans = (const float*)d_in[4];
    const float* scale = (const float*)d_in[5];
    const float* W1    = (const float*)d_in[6];
    const float* b1    = (const float*)d_in[7];
    const float* W2    = (const float*)d_in[8];
    const float* b2    = (const float*)d_in[9];
    float* out = (float*)d_out;

    tmat_fused_kernel<<<BATCH * 128, 256>>>(cond, W1, b1, W2, nodes,
                                            root, trans, scale, b2);
    knn_kernel<<<NTOT / 64, 128>>>(x, nodes, out);
}